// round 14
// baseline (speedup 1.0000x reference)
#include <cuda_runtime.h>
#include <math.h>

#define B_    256
#define S_    512
#define E_    256
#define H_    512
#define G3_   1536      // 3*H
#define VOCAB_ 32000

// ---------------- device scratch (no allocation allowed) ----------------
__device__ float d_VW[(size_t)VOCAB_ * G3_]; // emb @ Wx^T + b_ih  (196.6 MB)
__device__ float d_WxT [E_ * G3_];           // [k][g*512+u]  (w_ih_w cols 0..255)
__device__ float d_WhT [H_ * G3_];           // w_ih_w cols 256..767 transposed
__device__ float d_WhhT[H_ * G3_];           // w_hh_w transposed
__device__ float d_WipT[H_ * G3_];           // w_ih_p transposed
__device__ float d_WhpT[H_ * G3_];           // w_hh_p transposed
__device__ float d_pinT[H_ * H_];            // pin_w transposed [k][c]
__device__ float d_fusT[2 * H_ * H_];        // fus_w transposed
__device__ float d_h1T [H_ * H_];            // h1_w transposed
__device__ float d_hw[2][B_ * H_];           // worker hidden (permuted), double buffered
__device__ float d_hp[2][B_ * H_];           // planner hidden (permuted), double buffered
__device__ float d_HPP[B_ * G3_];            // hp @ WhT (permuted)
__device__ float d_pi [B_ * H_];             // planner input projection (permuted)
__device__ float d_fused[B_ * H_];
__device__ float d_relu [B_ * H_];
__device__ int   d_perm[B_];                 // sorted-rank -> original batch index
__device__ int   d_lens_s[B_];               // lengths sorted descending

// ---------------- math helpers ----------------
__device__ __forceinline__ float sigf(float x) {
    return 1.0f / (1.0f + __expf(-x));
}
__device__ __forceinline__ float tanh_fast(float x) {
    float ax = fabsf(x);
    float e  = __expf(-2.0f * ax);
    float t  = (1.0f - e) / (1.0f + e);
    return copysignf(t, x);
}
__device__ __forceinline__ unsigned long long pack2s(float v) {
    unsigned long long r;
    asm("mov.b64 %0, {%1, %1};" : "=l"(r) : "f"(v));
    return r;
}
__device__ __forceinline__ float2 unpack2(unsigned long long v) {
    float2 f;
    asm("mov.b64 {%0, %1}, %2;" : "=f"(f.x), "=f"(f.y) : "l"(v));
    return f;
}
// packed fp32 pair FMA: d += a*b elementwise on 2 lanes
__device__ __forceinline__ void ffma2(unsigned long long &d,
                                      unsigned long long a, unsigned long long b) {
    asm("fma.rn.f32x2 %0, %1, %2, %0;" : "+l"(d) : "l"(a), "l"(b));
}

// ---------------- init ----------------
__global__ void init_zero_kernel() {
    int i = blockIdx.x * blockDim.x + threadIdx.x;
    if (i < B_ * H_) { d_hw[0][i] = 0.0f; d_hp[0][i] = 0.0f; }
    if (i < B_ * G3_) d_HPP[i] = 0.0f;
}

// ---------------- sort batch rows by descending length (deterministic) ----------------
__global__ void sort_kernel(const int* __restrict__ lens) {
    __shared__ int L[B_];
    int i = threadIdx.x;
    L[i] = lens[i];
    __syncthreads();
    int li = L[i];
    int rank = 0;
    for (int j = 0; j < B_; j++) {
        int lj = L[j];
        if (lj > li || (lj == li && j < i)) rank++;
    }
    d_perm[rank]   = i;
    d_lens_s[rank] = li;
}

// ---------------- transpose all weight matrices ----------------
__global__ void transpose_all_kernel(
    const float* __restrict__ wihw, const float* __restrict__ whhw,
    const float* __restrict__ wihp, const float* __restrict__ whhp,
    const float* __restrict__ pinw, const float* __restrict__ fusw,
    const float* __restrict__ h1w)
{
    const float* src; float* dst; int R, K, ld, coff;
    switch (blockIdx.z) {
        case 0: src=wihw; dst=d_WxT;  R=G3_; K=E_;    ld=E_+H_; coff=0;   break;
        case 1: src=wihw; dst=d_WhT;  R=G3_; K=H_;    ld=E_+H_; coff=E_;  break;
        case 2: src=whhw; dst=d_WhhT; R=G3_; K=H_;    ld=H_;    coff=0;   break;
        case 3: src=wihp; dst=d_WipT; R=G3_; K=H_;    ld=H_;    coff=0;   break;
        case 4: src=whhp; dst=d_WhpT; R=G3_; K=H_;    ld=H_;    coff=0;   break;
        case 5: src=pinw; dst=d_pinT; R=H_;  K=H_;    ld=H_;    coff=0;   break;
        case 6: src=fusw; dst=d_fusT; R=H_;  K=2*H_;  ld=2*H_;  coff=0;   break;
        default:src=h1w;  dst=d_h1T;  R=H_;  K=H_;    ld=H_;    coff=0;   break;
    }
    __shared__ float tile[32][33];
    int r0 = blockIdx.y * 32, k0 = blockIdx.x * 32;
    int r = r0 + threadIdx.y, k = k0 + threadIdx.x;
    if (r < R && k < K) tile[threadIdx.y][threadIdx.x] = src[r * ld + coff + k];
    __syncthreads();
    int rr = r0 + threadIdx.x, kk = k0 + threadIdx.y;
    if (rr < R && kk < K) dst[(size_t)kk * R + rr] = tile[threadIdx.x][threadIdx.y];
}

// ======================= GEMM cores (lane = row, warp = 4 units) =======================
// Tile: 32 rows x 32 units x 3 gates. Block 256 threads, double-buffered smem,
// one __syncthreads per 32-k tile.
// A read: scalar LDS.32, conflict-free (banks (k+lane)%32).
// B read: broadcast LDS.128 per gate -> two f32x2 operands directly.
#define AS_STRIDE 33
#define AS_TILE   (32 * AS_STRIDE)   // 1056
#define BS3_TILE  (32 * 96)          // 3072
#define BS1_TILE  (32 * 32)          // 1024

__device__ __forceinline__ void gemm3v2(
    const float* __restrict__ A, int lda,
    const float* __restrict__ BT, int K,
    int m0, int u0,
    unsigned long long acc[3][2],
    float* __restrict__ As /*2*AS_TILE*/, float* __restrict__ Bs /*2*BS3_TILE*/)
{
    const int tid  = threadIdx.x;
    const int lane = tid & 31;
    const int ucol = (tid >> 5) << 2;      // warp's unit offset within tile
    const int am   = tid & 31;             // A loader: row
    const int akq  = (tid >> 5) << 2;      // A loader: 4 consecutive k
    const int bk   = tid >> 3;             // B loader: k row (0..31)
    const int boff = (tid & 7) << 2;       // B loader: 4 consecutive units
    const int NT   = K >> 5;

    // prologue: tile 0
    {
        float4 av = *(const float4*)(A + (size_t)(m0 + am) * lda + akq);
        const float* br = BT + (size_t)bk * G3_ + u0 + boff;
        float4 b0 = *(const float4*)(br);
        float4 b1 = *(const float4*)(br + H_);
        float4 b2 = *(const float4*)(br + 2 * H_);
        As[(akq + 0) * AS_STRIDE + am] = av.x;
        As[(akq + 1) * AS_STRIDE + am] = av.y;
        As[(akq + 2) * AS_STRIDE + am] = av.z;
        As[(akq + 3) * AS_STRIDE + am] = av.w;
        *(float4*)(Bs + bk * 96      + boff) = b0;
        *(float4*)(Bs + bk * 96 + 32 + boff) = b1;
        *(float4*)(Bs + bk * 96 + 64 + boff) = b2;
    }
    __syncthreads();

    for (int tile = 0; tile < NT; tile++) {
        float4 av2, c0, c1, c2;
        if (tile + 1 < NT) {
            int k0 = (tile + 1) << 5;
            av2 = *(const float4*)(A + (size_t)(m0 + am) * lda + k0 + akq);
            const float* brn = BT + (size_t)(k0 + bk) * G3_ + u0 + boff;
            c0 = *(const float4*)(brn);
            c1 = *(const float4*)(brn + H_);
            c2 = *(const float4*)(brn + 2 * H_);
        }
        const float* Ab = As + (tile & 1) * AS_TILE;
        const float* Bb = Bs + (tile & 1) * BS3_TILE;
        #pragma unroll
        for (int k = 0; k < 32; k++) {
            float a = Ab[k * AS_STRIDE + lane];
            unsigned long long aa = pack2s(a);
            double2 dr = *(const double2*)(Bb + k * 96      + ucol);
            double2 dz = *(const double2*)(Bb + k * 96 + 32 + ucol);
            double2 dn = *(const double2*)(Bb + k * 96 + 64 + ucol);
            ffma2(acc[0][0], aa, __double_as_longlong(dr.x));
            ffma2(acc[0][1], aa, __double_as_longlong(dr.y));
            ffma2(acc[1][0], aa, __double_as_longlong(dz.x));
            ffma2(acc[1][1], aa, __double_as_longlong(dz.y));
            ffma2(acc[2][0], aa, __double_as_longlong(dn.x));
            ffma2(acc[2][1], aa, __double_as_longlong(dn.y));
        }
        if (tile + 1 < NT) {
            float* An = As + ((tile + 1) & 1) * AS_TILE;
            float* Bn = Bs + ((tile + 1) & 1) * BS3_TILE;
            An[(akq + 0) * AS_STRIDE + am] = av2.x;
            An[(akq + 1) * AS_STRIDE + am] = av2.y;
            An[(akq + 2) * AS_STRIDE + am] = av2.z;
            An[(akq + 3) * AS_STRIDE + am] = av2.w;
            *(float4*)(Bn + bk * 96      + boff) = c0;
            *(float4*)(Bn + bk * 96 + 32 + boff) = c1;
            *(float4*)(Bn + bk * 96 + 64 + boff) = c2;
        }
        __syncthreads();
    }
}

// single-output variant (for pi): BT is [K][H_], tile 32 rows x 32 units
__device__ __forceinline__ void gemm1v2(
    const float* __restrict__ A,
    const float* __restrict__ BT, int K,
    int m0, int u0,
    unsigned long long acc[2],
    float* __restrict__ As /*2*AS_TILE*/, float* __restrict__ Bs /*2*BS1_TILE*/)
{
    const int tid  = threadIdx.x;
    const int lane = tid & 31;
    const int ucol = (tid >> 5) << 2;
    const int am   = tid & 31;
    const int akq  = (tid >> 5) << 2;
    const int bk   = tid >> 3;
    const int boff = (tid & 7) << 2;
    const int NT   = K >> 5;

    {
        float4 av = *(const float4*)(A + (size_t)(m0 + am) * H_ + akq);
        float4 b0 = *(const float4*)(BT + (size_t)bk * H_ + u0 + boff);
        As[(akq + 0) * AS_STRIDE + am] = av.x;
        As[(akq + 1) * AS_STRIDE + am] = av.y;
        As[(akq + 2) * AS_STRIDE + am] = av.z;
        As[(akq + 3) * AS_STRIDE + am] = av.w;
        *(float4*)(Bs + bk * 32 + boff) = b0;
    }
    __syncthreads();

    for (int tile = 0; tile < NT; tile++) {
        float4 av2, c0;
        if (tile + 1 < NT) {
            int k0 = (tile + 1) << 5;
            av2 = *(const float4*)(A + (size_t)(m0 + am) * H_ + k0 + akq);
            c0  = *(const float4*)(BT + (size_t)(k0 + bk) * H_ + u0 + boff);
        }
        const float* Ab = As + (tile & 1) * AS_TILE;
        const float* Bb = Bs + (tile & 1) * BS1_TILE;
        #pragma unroll
        for (int k = 0; k < 32; k++) {
            float a = Ab[k * AS_STRIDE + lane];
            unsigned long long aa = pack2s(a);
            double2 db = *(const double2*)(Bb + k * 32 + ucol);
            ffma2(acc[0], aa, __double_as_longlong(db.x));
            ffma2(acc[1], aa, __double_as_longlong(db.y));
        }
        if (tile + 1 < NT) {
            float* An = As + ((tile + 1) & 1) * AS_TILE;
            float* Bn = Bs + ((tile + 1) & 1) * BS1_TILE;
            An[(akq + 0) * AS_STRIDE + am] = av2.x;
            An[(akq + 1) * AS_STRIDE + am] = av2.y;
            An[(akq + 2) * AS_STRIDE + am] = av2.z;
            An[(akq + 3) * AS_STRIDE + am] = av2.w;
            *(float4*)(Bn + bk * 32 + boff) = c0;
        }
        __syncthreads();
    }
}

// unpack gate accumulators (2 x f32x2 over units) -> 4 unit values
__device__ __forceinline__ void unpackU(const unsigned long long a[2], float o[4]) {
    float2 v0 = unpack2(a[0]);
    float2 v1 = unpack2(a[1]);
    o[0] = v0.x; o[1] = v0.y; o[2] = v1.x; o[3] = v1.y;
}

// ---------------- VW = emb @ Wx^T + b_ih  (whole vocab, once) ----------------
// grid (16, 1000), block 256
__global__ __launch_bounds__(256) void vw_gemm_kernel(
    const float* __restrict__ emb, const float* __restrict__ bihw)
{
    __shared__ __align__(16) float As[2 * AS_TILE];
    __shared__ __align__(16) float Bs[2 * BS3_TILE];
    unsigned long long acc[3][2] = {};
    int u0 = blockIdx.x * 32, m0 = blockIdx.y * 32;
    gemm3v2(emb, E_, d_WxT, E_, m0, u0, acc, As, Bs);
    int lane = threadIdx.x & 31, ucol = (threadIdx.x >> 5) << 2;
    size_t m = m0 + lane;
    int u = u0 + ucol;
    float gr[4], gz[4], gn[4];
    unpackU(acc[0], gr); unpackU(acc[1], gz); unpackU(acc[2], gn);
    float4 br = *(const float4*)(bihw + u);
    float4 bz = *(const float4*)(bihw + H_ + u);
    float4 bn = *(const float4*)(bihw + 2 * H_ + u);
    float4 o;
    o.x = gr[0] + br.x; o.y = gr[1] + br.y; o.z = gr[2] + br.z; o.w = gr[3] + br.w;
    *(float4*)(d_VW + m * G3_ + u) = o;
    o.x = gz[0] + bz.x; o.y = gz[1] + bz.y; o.z = gz[2] + bz.z; o.w = gz[3] + bz.w;
    *(float4*)(d_VW + m * G3_ + H_ + u) = o;
    o.x = gn[0] + bn.x; o.y = gn[1] + bn.y; o.z = gn[2] + bn.z; o.w = gn[3] + bn.w;
    *(float4*)(d_VW + m * G3_ + 2 * H_ + u) = o;
}

// ---------------- worker GRU step ----------------
// grid (16, 8), block 256; frozen-block early exit
__global__ __launch_bounds__(256) void worker_step_kernel(
    const int* __restrict__ ids, const float* __restrict__ bhh, int t)
{
    int u0 = blockIdx.x * 32, m0 = blockIdx.y * 32;
    if (d_lens_s[m0] <= t - 2) return;
    __shared__ __align__(16) float As[2 * AS_TILE];
    __shared__ __align__(16) float Bs[2 * BS3_TILE];
    const float* __restrict__ hwin = d_hw[t & 1];
    float* __restrict__ hwout      = d_hw[(t + 1) & 1];
    unsigned long long acc[3][2] = {};
    gemm3v2(hwin, H_, d_WhhT, H_, m0, u0, acc, As, Bs);

    int lane = threadIdx.x & 31, ucol = (threadIdx.x >> 5) << 2;
    int m = m0 + lane;
    int u = u0 + ucol;
    int len = d_lens_s[m];
    int id  = ids[d_perm[m] * S_ + t];
    const float* vw  = d_VW  + (size_t)id * G3_;
    const float* hpp = d_HPP + (size_t)m  * G3_;
    float4 vr = *(const float4*)(vw + u);
    float4 vz = *(const float4*)(vw + H_ + u);
    float4 vn = *(const float4*)(vw + 2 * H_ + u);
    float4 pr = *(const float4*)(hpp + u);
    float4 pz = *(const float4*)(hpp + H_ + u);
    float4 pn = *(const float4*)(hpp + 2 * H_ + u);
    float4 hb = *(const float4*)(hwin + m * H_ + u);
    float4 Br = *(const float4*)(bhh + u);
    float4 Bz = *(const float4*)(bhh + H_ + u);
    float4 Bn = *(const float4*)(bhh + 2 * H_ + u);
    float ar[4], az[4], an[4];
    unpackU(acc[0], ar); unpackU(acc[1], az); unpackU(acc[2], an);
    float vvr[4] = {vr.x, vr.y, vr.z, vr.w}, vvz[4] = {vz.x, vz.y, vz.z, vz.w},
          vvn[4] = {vn.x, vn.y, vn.z, vn.w};
    float ppr[4] = {pr.x, pr.y, pr.z, pr.w}, ppz[4] = {pz.x, pz.y, pz.z, pz.w},
          ppn[4] = {pn.x, pn.y, pn.z, pn.w};
    float hh[4]  = {hb.x, hb.y, hb.z, hb.w};
    float bbr[4] = {Br.x, Br.y, Br.z, Br.w}, bbz[4] = {Bz.x, Bz.y, Bz.z, Bz.w},
          bbn[4] = {Bn.x, Bn.y, Bn.z, Bn.w};
    float res[4];
    bool active = (t < len);
    #pragma unroll
    for (int j = 0; j < 4; j++) {
        float r = sigf(vvr[j] + ppr[j] + ar[j] + bbr[j]);
        float z = sigf(vvz[j] + ppz[j] + az[j] + bbz[j]);
        float n = tanh_fast(vvn[j] + ppn[j] + r * (an[j] + bbn[j]));
        float hnew = (1.0f - z) * n + z * hh[j];
        res[j] = active ? hnew : hh[j];
    }
    *(float4*)(hwout + m * H_ + u) = make_float4(res[0], res[1], res[2], res[3]);
}

// ---------------- planner: pi = hw @ pin^T + pin_b ----------------
// grid (16, 8), block 256
__global__ __launch_bounds__(256) void pi_kernel(const float* __restrict__ pinb, int t)
{
    int u0 = blockIdx.x * 32, m0 = blockIdx.y * 32;
    if (d_lens_s[m0] <= t - 8) return;
    __shared__ __align__(16) float As[2 * AS_TILE];
    __shared__ __align__(16) float Bs[2 * BS1_TILE];
    const float* __restrict__ hw = d_hw[(t + 1) & 1];
    unsigned long long acc[2] = {};
    gemm1v2(hw, d_pinT, H_, m0, u0, acc, As, Bs);
    int lane = threadIdx.x & 31, ucol = (threadIdx.x >> 5) << 2;
    int m = m0 + lane;
    int u = u0 + ucol;
    float a[4]; unpackU(acc, a);
    float4 bb = *(const float4*)(pinb + u);
    *(float4*)(d_pi + m * H_ + u) =
        make_float4(a[0] + bb.x, a[1] + bb.y, a[2] + bb.z, a[3] + bb.w);
}

// ---------------- planner GRU gates + update ----------------
// grid (16, 8), block 256
__global__ __launch_bounds__(256) void planner_step_kernel(
    const float* __restrict__ bip, const float* __restrict__ bhp, int t, int p)
{
    int u0 = blockIdx.x * 32, m0 = blockIdx.y * 32;
    if (d_lens_s[m0] <= t - 8) return;
    __shared__ __align__(16) float As[2 * AS_TILE];
    __shared__ __align__(16) float Bs[2 * BS3_TILE];
    const float* __restrict__ hpin = d_hp[p & 1];
    float* __restrict__ hpout      = d_hp[(p + 1) & 1];
    unsigned long long acci[3][2] = {};
    unsigned long long acch[3][2] = {};
    gemm3v2(d_pi, H_, d_WipT, H_, m0, u0, acci, As, Bs);
    gemm3v2(hpin, H_, d_WhpT, H_, m0, u0, acch, As, Bs);

    int lane = threadIdx.x & 31, ucol = (threadIdx.x >> 5) << 2;
    int m = m0 + lane;
    int u = u0 + ucol;
    int len = d_lens_s[m];
    float4 Bir = *(const float4*)(bip + u);
    float4 Biz = *(const float4*)(bip + H_ + u);
    float4 Bin = *(const float4*)(bip + 2 * H_ + u);
    float4 Bhr = *(const float4*)(bhp + u);
    float4 Bhz = *(const float4*)(bhp + H_ + u);
    float4 Bhn = *(const float4*)(bhp + 2 * H_ + u);
    float4 hb  = *(const float4*)(hpin + m * H_ + u);
    float ir[4], iz[4], in_[4], hr[4], hz[4], hn[4];
    unpackU(acci[0], ir); unpackU(acci[1], iz); unpackU(acci[2], in_);
    unpackU(acch[0], hr); unpackU(acch[1], hz); unpackU(acch[2], hn);
    float bir[4] = {Bir.x, Bir.y, Bir.z, Bir.w}, biz[4] = {Biz.x, Biz.y, Biz.z, Biz.w},
          bin[4] = {Bin.x, Bin.y, Bin.z, Bin.w};
    float bhr[4] = {Bhr.x, Bhr.y, Bhr.z, Bhr.w}, bhz[4] = {Bhz.x, Bhz.y, Bhz.z, Bhz.w},
          bhn[4] = {Bhn.x, Bhn.y, Bhn.z, Bhn.w};
    float hh[4]  = {hb.x, hb.y, hb.z, hb.w};
    float res[4];
    bool active = (t < len);
    #pragma unroll
    for (int j = 0; j < 4; j++) {
        float r = sigf(ir[j] + bir[j] + hr[j] + bhr[j]);
        float z = sigf(iz[j] + biz[j] + hz[j] + bhz[j]);
        float n = tanh_fast(in_[j] + bin[j] + r * (hn[j] + bhn[j]));
        float hnew = (1.0f - z) * n + z * hh[j];
        res[j] = active ? hnew : hh[j];
    }
    *(float4*)(hpout + m * H_ + u) = make_float4(res[0], res[1], res[2], res[3]);
}

// ---------------- HPP = hp @ WhT  (refresh after planner update) ----------------
// grid (16, 8), block 256
__global__ __launch_bounds__(256) void hpp_kernel(int t, int p)
{
    int u0 = blockIdx.x * 32, m0 = blockIdx.y * 32;
    if (d_lens_s[m0] <= t - 8) return;
    __shared__ __align__(16) float As[2 * AS_TILE];
    __shared__ __align__(16) float Bs[2 * BS3_TILE];
    const float* __restrict__ hp = d_hp[(p + 1) & 1];
    unsigned long long acc[3][2] = {};
    gemm3v2(hp, H_, d_WhT, H_, m0, u0, acc, As, Bs);
    int lane = threadIdx.x & 31, ucol = (threadIdx.x >> 5) << 2;
    size_t m = m0 + lane;
    int u = u0 + ucol;
    float ar[4], az[4], an[4];
    unpackU(acc[0], ar); unpackU(acc[1], az); unpackU(acc[2], an);
    *(float4*)(d_HPP + m * G3_ + u)          = make_float4(ar[0], ar[1], ar[2], ar[3]);
    *(float4*)(d_HPP + m * G3_ + H_ + u)     = make_float4(az[0], az[1], az[2], az[3]);
    *(float4*)(d_HPP + m * G3_ + 2 * H_ + u) = make_float4(an[0], an[1], an[2], an[3]);
}

// ---------------- fused = tanh([hw,hp] @ fus^T + fus_b) ----------------
__global__ __launch_bounds__(256) void fusion_kernel(const float* __restrict__ fusb)
{
    __shared__ __align__(16) float As[2 * AS_TILE];
    __shared__ __align__(16) float Bs[2 * BS1_TILE];
    int u0 = blockIdx.x * 32, m0 = blockIdx.y * 32;
    unsigned long long acc[2] = {};
    gemm1v2(d_hw[0], d_fusT, H_, m0, u0, acc, As, Bs);          // first half of K
    gemm1v2(d_hp[0], d_fusT + (size_t)H_ * H_, H_, m0, u0, acc, As, Bs); // second half
    int lane = threadIdx.x & 31, ucol = (threadIdx.x >> 5) << 2;
    int m = m0 + lane;
    int u = u0 + ucol;
    float a[4]; unpackU(acc, a);
    float4 bb = *(const float4*)(fusb + u);
    float4 o;
    o.x = tanh_fast(a[0] + bb.x); o.y = tanh_fast(a[1] + bb.y);
    o.z = tanh_fast(a[2] + bb.z); o.w = tanh_fast(a[3] + bb.w);
    *(float4*)(d_fused + m * H_ + u) = o;
}

// ---------------- h = relu(fused @ h1^T + h1_b) ----------------
__global__ __launch_bounds__(256) void h1_kernel(const float* __restrict__ h1b)
{
    __shared__ __align__(16) float As[2 * AS_TILE];
    __shared__ __align__(16) float Bs[2 * BS1_TILE];
    int u0 = blockIdx.x * 32, m0 = blockIdx.y * 32;
    unsigned long long acc[2] = {};
    gemm1v2(d_fused, d_h1T, H_, m0, u0, acc, As, Bs);
    int lane = threadIdx.x & 31, ucol = (threadIdx.x >> 5) << 2;
    int m = m0 + lane;
    int u = u0 + ucol;
    float a[4]; unpackU(acc, a);
    float4 bb = *(const float4*)(h1b + u);
    float4 o;
    o.x = fmaxf(a[0] + bb.x, 0.0f); o.y = fmaxf(a[1] + bb.y, 0.0f);
    o.z = fmaxf(a[2] + bb.z, 0.0f); o.w = fmaxf(a[3] + bb.w, 0.0f);
    *(float4*)(d_relu + m * H_ + u) = o;
}

// ---------------- out = h @ h2^T + h2_b (un-permutes rows) ----------------
__global__ void out_kernel(const float* __restrict__ h2w, const float* __restrict__ h2b,
                           float* __restrict__ out)
{
    int b = blockIdx.x;                 // permuted row
    int c = threadIdx.x >> 5;           // 0..9
    int lane = threadIdx.x & 31;
    float s = 0.0f;
    const float* hrow = d_relu + b * H_;
    const float* wrow = h2w + c * H_;
    for (int k = lane; k < H_; k += 32) s += hrow[k] * wrow[k];
    #pragma unroll
    for (int o = 16; o; o >>= 1) s += __shfl_down_sync(0xffffffff, s, o);
    if (lane == 0) out[d_perm[b] * 10 + c] = s + h2b[c];
}

// ---------------- host launcher (graph-capturable, no allocs) ----------------
extern "C" void kernel_launch(void* const* d_in, const int* in_sizes, int n_in,
                              void* d_out, int out_size)
{
    (void)in_sizes; (void)n_in; (void)out_size;
    const int*   ids  = (const int*)  d_in[0];
    const int*   lens = (const int*)  d_in[1];
    const float* emb  = (const float*)d_in[2];
    const float* wihw = (const float*)d_in[3];
    const float* whhw = (const float*)d_in[4];
    const float* bihw = (const float*)d_in[5];
    const float* bhhw = (const float*)d_in[6];
    const float* pinw = (const float*)d_in[7];
    const float* pinb = (const float*)d_in[8];
    const float* wihp = (const float*)d_in[9];
    const float* whhp = (const float*)d_in[10];
    const float* bihp = (const float*)d_in[11];
    const float* bhhp = (const float*)d_in[12];
    const float* fusw = (const float*)d_in[13];
    const float* fusb = (const float*)d_in[14];
    const float* h1w  = (const float*)d_in[15];
    const float* h1b  = (const float*)d_in[16];
    const float* h2w  = (const float*)d_in[17];
    const float* h2b  = (const float*)d_in[18];
    float* out = (float*)d_out;

    init_zero_kernel<<<(B_ * G3_ + 255) / 256, 256>>>();
    sort_kernel<<<1, B_>>>(lens);
    transpose_all_kernel<<<dim3(32, 48, 8), dim3(32, 32)>>>(
        wihw, whhw, wihp, whhp, pinw, fusw, h1w);
    vw_gemm_kernel<<<dim3(16, VOCAB_ / 32), 256>>>(emb, bihw);

    for (int t = 0; t < S_; t++) {
        worker_step_kernel<<<dim3(16, 8), 256>>>(ids, bhhw, t);
        if (((t + 1) & 3) == 0) {
            int p = ((t + 1) >> 2) - 1;          // 0..127
            pi_kernel<<<dim3(16, 8), 256>>>(pinb, t);
            planner_step_kernel<<<dim3(16, 8), 256>>>(bihp, bhhp, t, p);
            hpp_kernel<<<dim3(16, 8), 256>>>(t, p);
        }
    }

    fusion_kernel<<<dim3(16, 8), 256>>>(fusb);
    h1_kernel<<<dim3(16, 8), 256>>>(h1b);
    out_kernel<<<B_, 320>>>(h2w, h2b, out);
}